// round 11
// baseline (speedup 1.0000x reference)
#include <cuda_runtime.h>
#include <cuda_fp16.h>
#include <math.h>

#define Hh 96
#define Ww 128
#define Dd 64
#define Bb 8
#define Kk 7
#define Cc 32
#define HW (Hh*Ww)
#define EPSF 1e-8f
#define DCH 8

// Scratch (allocation-free rule: static __device__ arrays)
__device__ __half g_srcH[(size_t)Bb*Kk*HW*Cc];   // (B,K,H,W,C) channels-last fp16, 44MB
__device__ __half g_curH[(size_t)Bb*HW*Cc];      // (B,H,W,C) fp16, 6.3MB
__device__ float  g_Q[Bb*Kk*12];                 // per (b,k): Q(3x3) row-major + t(3)

// ---------------- setup: per-(b,k) projection matrices ----------------
__global__ void setup_kernel(const float* __restrict__ E,
                             const float* __restrict__ Ks,
                             const float* __restrict__ invK)
{
    int bk = blockIdx.x * blockDim.x + threadIdx.x;
    if (bk >= Bb*Kk) return;
    int b = bk / Kk;
    const float* e  = E   + bk * 16;
    const float* km = Ks  + bk * 16;
    const float* ik = invK + b * 16;
    float P[3][4];
    #pragma unroll
    for (int r = 0; r < 3; ++r)
        #pragma unroll
        for (int c = 0; c < 4; ++c) {
            float s = 0.f;
            #pragma unroll
            for (int j = 0; j < 4; ++j) s += km[r*4+j] * e[j*4+c];
            P[r][c] = s;
        }
    #pragma unroll
    for (int r = 0; r < 3; ++r)
        #pragma unroll
        for (int c = 0; c < 3; ++c) {
            float s = 0.f;
            #pragma unroll
            for (int j = 0; j < 3; ++j) s += P[r][j] * ik[j*4+c];
            g_Q[bk*12 + r*3 + c] = s;
        }
    #pragma unroll
    for (int r = 0; r < 3; ++r) g_Q[bk*12 + 9 + r] = P[r][3];
}

// -------- transpose+convert (nmaps, C=32, HW) fp32 -> (nmaps, HW, C=32) fp16 --------
__global__ void transpose_kernel(const float* __restrict__ in, __half* __restrict__ outp)
{
    __shared__ float tile[32][33];
    int m  = blockIdx.z;
    int p0 = blockIdx.x * 32;
    int tx = threadIdx.x;     // 0..31
    int ty = threadIdx.y;     // 0..7
    #pragma unroll
    for (int j = 0; j < 4; ++j) {
        int c = ty + j*8;
        tile[c][tx] = in[((size_t)m*Cc + c)*HW + p0 + tx];
    }
    __syncthreads();
    #pragma unroll
    for (int j = 0; j < 4; ++j) {
        int pr = ty + j*8;
        outp[((size_t)m*HW + p0 + pr)*Cc + tx] = __float2half(tile[tx][pr]);
    }
}

// ---------------- main cost-volume kernel ----------------
// ONE THREAD PER PIXEL: thread owns full C=32 dot (16 half2 cur regs).
// Block: 256 threads covering 256 consecutive pixels (2 rows).
// Loops: d-chunk(8) outer, k middle, d inner; fp32 acc over k in registers.
// No shfl reduction; direct coalesced STG per depth.
__global__ __launch_bounds__(256) void cost_kernel(const float* __restrict__ mind,
                                                   const float* __restrict__ maxd,
                                                   float* __restrict__ out)
{
    __shared__ float s_depth[Dd];
    __shared__ float s_q[Kk*12];

    const int tid  = threadIdx.x;
    const int p_g  = blockIdx.x * 256 + tid;   // global pixel (b*HW + p)
    const int b    = p_g / HW;
    const int p    = p_g % HW;

    if (tid < Dd) {
        float mn = mind[b], mx = maxd[b];
        s_depth[tid] = expf(logf(mn) + logf(mx/mn) * ((float)tid / 63.0f));
    }
    if (tid < Kk*12) s_q[tid] = g_Q[b*Kk*12 + tid];
    __syncthreads();

    // current-frame features: all 32 channels as 16 half2
    __half2 c[16];
    {
        const float4* cp = (const float4*)(g_curH + (size_t)p_g*Cc);
        #pragma unroll
        for (int i = 0; i < 4; ++i) {
            const float4 cv = cp[i];
            c[i*4+0] = *(const __half2*)&cv.x;
            c[i*4+1] = *(const __half2*)&cv.y;
            c[i*4+2] = *(const __half2*)&cv.z;
            c[i*4+3] = *(const __half2*)&cv.w;
        }
    }

    const int py = p >> 7;                 // / W
    const int px = p & (Ww-1);
    const float u0 = px + 0.5f;
    const float v0 = py + 0.5f;
    const __half* __restrict__ srcb0 = g_srcH + (size_t)b*Kk*HW*Cc;

    for (int dc = 0; dc < Dd; dc += DCH) {
        float acc[DCH];
        float deps[DCH];
        #pragma unroll
        for (int j = 0; j < DCH; ++j) { acc[j] = 0.f; deps[j] = s_depth[dc + j]; }

        for (int k = 0; k < Kk; ++k) {
            const float* q = s_q + k*12;
            const float Ax = fmaf(q[0], u0, fmaf(q[1], v0, q[2]));
            const float Ay = fmaf(q[3], u0, fmaf(q[4], v0, q[5]));
            const float Az = fmaf(q[6], u0, fmaf(q[7], v0, q[8]));
            const float Tx = q[9], Ty = q[10], Tz = q[11];
            const __half* __restrict__ srcbase = srcb0 + (size_t)k*HW*Cc;

            #pragma unroll
            for (int j = 0; j < DCH; ++j) {
                const float dep  = deps[j];
                const float camx = fmaf(dep, Ax, Tx);
                const float camy = fmaf(dep, Ay, Ty);
                const float camz = fmaf(dep, Az, Tz);
                const float z    = camz + EPSF;
                const float scale = (fabsf(camz) > EPSF) ? (1.0f / z) : 1.0f;
                const float x = fmaf(camx, scale, -0.5f);
                const float y = fmaf(camy, scale, -0.5f);
                const float fx = floorf(x), fy = floorf(y);
                const float wx = x - fx,    wy = y - fy;
                const int ix = __float2int_rz(fx);
                const int iy = __float2int_rz(fy);
                const int ix1 = ix + 1, iy1 = iy + 1;
                const bool zok = (z > 0.f);

                // 1-D validity weights: unsigned compare covers both bounds
                const float wx0v = ((unsigned)ix  <= (unsigned)(Ww-1)) ? (1.f - wx) : 0.f;
                const float wx1v = ((unsigned)ix1 <= (unsigned)(Ww-1)) ? wx         : 0.f;
                const float wy0v = (zok & ((unsigned)iy  <= (unsigned)(Hh-1))) ? (1.f - wy) : 0.f;
                const float wy1v = (zok & ((unsigned)iy1 <= (unsigned)(Hh-1))) ? wy         : 0.f;

                // addresses: x masked (weight 0 when out of range), y clamped
                const int col0 = (ix  & (Ww-1)) << 5;
                const int col1 = (ix1 & (Ww-1)) << 5;
                const int row0 = min(max(iy,  0), Hh-1) << 12;
                const int row1 = min(max(iy1, 0), Hh-1) << 12;

                const float w00 = wx0v * wy0v;
                const float w01 = wx1v * wy0v;
                const float w10 = wx0v * wy1v;
                const float w11 = wx1v * wy1v;
                const int off00 = row0 + col0;
                const int off01 = row0 + col1;
                const int off10 = row1 + col0;
                const int off11 = row1 + col1;

                float sum = acc[j];
                #pragma unroll
                for (int t2 = 0; t2 < 4; ++t2) {
                    const int   off = (t2 == 0) ? off00 : (t2 == 1) ? off01 : (t2 == 2) ? off10 : off11;
                    const float w   = (t2 == 0) ? w00  : (t2 == 1) ? w01  : (t2 == 2) ? w10  : w11;
                    const float4* vp = (const float4*)(srcbase + off);
                    const float4 va = vp[0];   // ch 0-7
                    const float4 vb = vp[1];   // ch 8-15
                    const float4 vc = vp[2];   // ch 16-23
                    const float4 vd = vp[3];   // ch 24-31
                    // two independent 8-deep half2 chains (error control)
                    __half2 dA = __hmul2(*(const __half2*)&va.x, c[0]);
                    dA = __hfma2(*(const __half2*)&va.y, c[1], dA);
                    dA = __hfma2(*(const __half2*)&va.z, c[2], dA);
                    dA = __hfma2(*(const __half2*)&va.w, c[3], dA);
                    dA = __hfma2(*(const __half2*)&vb.x, c[4], dA);
                    dA = __hfma2(*(const __half2*)&vb.y, c[5], dA);
                    dA = __hfma2(*(const __half2*)&vb.z, c[6], dA);
                    dA = __hfma2(*(const __half2*)&vb.w, c[7], dA);
                    __half2 dB = __hmul2(*(const __half2*)&vc.x, c[8]);
                    dB = __hfma2(*(const __half2*)&vc.y, c[9],  dB);
                    dB = __hfma2(*(const __half2*)&vc.z, c[10], dB);
                    dB = __hfma2(*(const __half2*)&vc.w, c[11], dB);
                    dB = __hfma2(*(const __half2*)&vd.x, c[12], dB);
                    dB = __hfma2(*(const __half2*)&vd.y, c[13], dB);
                    dB = __hfma2(*(const __half2*)&vd.z, c[14], dB);
                    dB = __hfma2(*(const __half2*)&vd.w, c[15], dB);
                    const float2 fa = __half22float2(dA);
                    const float2 fb = __half22float2(dB);
                    sum = fmaf(w, (fa.x + fa.y) + (fb.x + fb.y), sum);
                }
                acc[j] = sum;
            }
        }

        // store (coalesced 128B per warp per depth)
        #pragma unroll
        for (int j = 0; j < DCH; ++j)
            out[((size_t)(b*Dd + dc + j))*HW + p] = acc[j];
    }
}

extern "C" void kernel_launch(void* const* d_in, const int* in_sizes, int n_in,
                              void* d_out, int out_size)
{
    const float* cur_feats = (const float*)d_in[0];
    const float* src_feats = (const float*)d_in[1];
    const float* src_E     = (const float*)d_in[2];
    const float* src_Ks    = (const float*)d_in[3];
    const float* cur_invK  = (const float*)d_in[4];
    const float* min_depth = (const float*)d_in[5];
    const float* max_depth = (const float*)d_in[6];
    float* out = (float*)d_out;

    __half* srcH; cudaGetSymbolAddress((void**)&srcH, g_srcH);
    __half* curH; cudaGetSymbolAddress((void**)&curH, g_curH);

    setup_kernel<<<1, 64>>>(src_E, src_Ks, cur_invK);

    dim3 tb(32, 8);
    dim3 tg_src(HW/32, 1, Bb*Kk);
    transpose_kernel<<<tg_src, tb>>>(src_feats, srcH);
    dim3 tg_cur(HW/32, 1, Bb);
    transpose_kernel<<<tg_cur, tb>>>(cur_feats, curH);

    cost_kernel<<<(Bb*HW)/256, 256>>>(min_depth, max_depth, out);
}